// round 5
// baseline (speedup 1.0000x reference)
#include <cuda_runtime.h>
#include <cuda_fp16.h>
#include <math.h>

#define BB 2
#define NQ 256
#define NK 2048
#define DIM 256
#define NH 8
#define HD 32
#define NPTS 8
#define NCELL 1000

#define SST (NK + 8)             // padded score row stride (floats)

// scratch (device globals — no allocation allowed)
__device__ __half g_tables[NPTS * NCELL * NH];  // [i][cell=z*100+y*10+x][h], fp16
__device__ float g_qproj[BB * NQ * DIM];
__device__ float g_kproj[BB * NK * HD];
__device__ float g_vproj[BB * NK * HD];
__device__ float g_xmid [BB * NQ * DIM];
__device__ float g_scores[(size_t)BB * NQ * NH * NK];   // [bq][h][k], raw RPE

// -------------------- CPB tables --------------------
__global__ void k_tables(const float* __restrict__ w1, const float* __restrict__ b1,
                         const float* __restrict__ w2) {
    int gid = blockIdx.x * blockDim.x + threadIdx.x;
    if (gid >= NPTS * NCELL) return;
    int i = gid / NCELL;
    int cell = gid % NCELL;
    int p = cell / 100, q = (cell / 10) % 10, r = cell % 10;
    const float step = 8.0f / 9.0f;
    float lp = -4.0f + p * step, lq = -4.0f + q * step, lr = -4.0f + r * step;
    const float* w1i = w1 + i * 3 * 128;
    const float* b1i = b1 + i * 128;
    const float* w2i = w2 + i * 128 * 8;
    float acc[8] = {0,0,0,0,0,0,0,0};
    for (int d = 0; d < 128; d++) {
        float h = lp * w1i[d] + lq * w1i[128 + d] + lr * w1i[256 + d] + b1i[d];
        h = fmaxf(h, 0.0f);
        const float* w2d = w2i + d * 8;
        #pragma unroll
        for (int hh = 0; hh < 8; hh++) acc[hh] += h * w2d[hh];
    }
    __half* out = g_tables + gid * 8;
    #pragma unroll
    for (int hh = 0; hh < 8; hh++) out[hh] = __float2half(acc[hh]);
}

// -------------------- Q projection --------------------
__global__ void k_qproj(const float* __restrict__ query, const float* __restrict__ w,
                        const float* __restrict__ bias) {
    __shared__ float row[DIM];
    int rid = blockIdx.x;               // b*NQ + nq
    int b = rid >> 8, nq = rid & 255;
    int t = threadIdx.x;
    row[t] = query[(nq * BB + b) * DIM + t];   // query is (nQ, B, DIM)
    __syncthreads();
    float acc = bias[t];
    #pragma unroll 4
    for (int c = 0; c < DIM; c++) acc += row[c] * w[c * DIM + t];
    g_qproj[rid * DIM + t] = acc;
}

// -------------------- K/V projection --------------------
__global__ void k_kvproj(const float* __restrict__ key,
                         const float* __restrict__ kw, const float* __restrict__ kb,
                         const float* __restrict__ vw, const float* __restrict__ vb) {
    __shared__ float row[DIM];
    int rid = blockIdx.x;               // b*NK + kk
    int b = rid >> 11, kk = rid & 2047;
    int t = threadIdx.x;                // 64 threads
    for (int c = t; c < DIM; c += 64) row[c] = key[(kk * BB + b) * DIM + c];
    __syncthreads();
    int j = t & 31;
    const float* w  = (t < 32) ? kw : vw;
    float acc       = (t < 32) ? kb[j] : vb[j];
    #pragma unroll 4
    for (int c = 0; c < DIM; c++) acc += row[c] * w[c * HD + j];
    if (t < 32) g_kproj[rid * HD + j] = acc;
    else        g_vproj[rid * HD + j] = acc;
}

// -------------------- RPE helpers --------------------
__device__ __forceinline__ float xform(float dd) {
    float g = __log2f(fabsf(dd) * 512.0f + 1.0f) * (1.0f / 12.0f);
    return copysignf(g, dd);
}

__device__ __forceinline__ void axis_setup(float f, int scale, int* o, float* w) {
    float f0 = floorf(f);
    int i0 = (int)f0;
    float w1 = f - f0;
    int c0 = min(max(i0, 0), 9);
    int c1 = min(max(i0 + 1, 0), 9);
    o[0] = c0 * scale;
    o[1] = c1 * scale;
    w[0] = ((unsigned)i0 < 10u) ? 1.0f - w1 : 0.0f;
    w[1] = ((unsigned)(i0 + 1) < 10u) ? w1 : 0.0f;
}

// -------------------- RPE kernel: 2 in-kernel table stages --------------------
// block = bq*2 + kh (k-half), 256 threads, KPT=4, smem 64 KB (4 tables)
#define RPE_THREADS 256
#define RPE_KPT 4
#define TBL_HALVES_PER_STAGE (4 * NCELL * NH)      // 32000 halves = 64000 B

__global__ void __launch_bounds__(RPE_THREADS, 3)
k_rpe(const float* __restrict__ refpt, const float* __restrict__ xyz) {
    extern __shared__ __half s_tblr[];             // 32000 halves
    __shared__ float s_rp[24];
    int t = threadIdx.x;
    int blk = blockIdx.x;
    int kh = blk & 1;
    int bq = blk >> 1;
    int b = bq >> 8;

    if (t < 24) s_rp[t] = refpt[bq * 24 + t];

    __half2 hacc[RPE_KPT][4];
    #pragma unroll
    for (int m = 0; m < RPE_KPT; m++)
        #pragma unroll
        for (int j = 0; j < 4; j++) hacc[m][j] = __float2half2_rn(0.f);

    #pragma unroll 1
    for (int stage = 0; stage < 2; stage++) {
        __syncthreads();   // stage 0: orders s_rp; stage 1: protects table overwrite
        {
            const uint4* src = (const uint4*)g_tables + stage * (TBL_HALVES_PER_STAGE / 8);
            uint4* dst = (uint4*)s_tblr;
            #pragma unroll 1
            for (int idx = t; idx < TBL_HALVES_PER_STAGE / 8; idx += RPE_THREADS)
                dst[idx] = src[idx];
        }
        __syncthreads();

        #pragma unroll 1
        for (int m = 0; m < RPE_KPT; m++) {
            int k = kh * 1024 + m * RPE_THREADS + t;
            const float* xv = xyz + (b * NK + k) * 3;
            float kx = xv[0], ky = xv[1], kz = xv[2];
            #pragma unroll 2
            for (int ii = 0; ii < 4; ii++) {
                int i = stage * 4 + ii;
                float gx = xform(s_rp[i*3+0] - kx);
                float gy = xform(s_rp[i*3+1] - ky);
                float gz = xform(s_rp[i*3+2] - kz);
                float fx = fmaf(gx, 4.5f, 4.5f);
                float fy = fmaf(gy, 4.5f, 4.5f);
                float fz = fmaf(gz, 4.5f, 4.5f);
                int oxa[2], oya[2], oza[2];
                float wxa[2], wya[2], wza[2];
                axis_setup(fx, NH,       oxa, wxa);
                axis_setup(fy, NH * 10,  oya, wya);
                axis_setup(fz, NH * 100, oza, wza);
                float wzy[4] = {wza[0]*wya[0], wza[0]*wya[1], wza[1]*wya[0], wza[1]*wya[1]};
                int ozy[4];
                ozy[0] = oza[0]+oya[0]; ozy[1] = oza[0]+oya[1];
                ozy[2] = oza[1]+oya[0]; ozy[3] = oza[1]+oya[1];
                const __half* base = s_tblr + ii * (NCELL * NH);
                uint4 raw[8];
                #pragma unroll
                for (int c = 0; c < 8; c++)
                    raw[c] = *(const uint4*)(base + ozy[c >> 1] + oxa[c & 1]);
                #pragma unroll
                for (int c = 0; c < 8; c++) {
                    float w = wzy[c >> 1] * wxa[c & 1];
                    __half2 wh = __float2half2_rn(w);
                    hacc[m][0] = __hfma2(wh, *(const __half2*)&raw[c].x, hacc[m][0]);
                    hacc[m][1] = __hfma2(wh, *(const __half2*)&raw[c].y, hacc[m][1]);
                    hacc[m][2] = __hfma2(wh, *(const __half2*)&raw[c].z, hacc[m][2]);
                    hacc[m][3] = __hfma2(wh, *(const __half2*)&raw[c].w, hacc[m][3]);
                }
            }
        }
    }

    // write raw RPE to gmem: g_scores[bq][h][k]
    #pragma unroll
    for (int m = 0; m < RPE_KPT; m++) {
        int k = kh * 1024 + m * RPE_THREADS + t;
        float* sp = g_scores + (size_t)bq * NH * NK + k;
        float2 f0 = __half22float2(hacc[m][0]);
        float2 f1 = __half22float2(hacc[m][1]);
        float2 f2 = __half22float2(hacc[m][2]);
        float2 f3 = __half22float2(hacc[m][3]);
        sp[0 * NK] = f0.x; sp[1 * NK] = f0.y;
        sp[2 * NK] = f1.x; sp[3 * NK] = f1.y;
        sp[4 * NK] = f2.x; sp[5 * NK] = f2.y;
        sp[6 * NK] = f3.x; sp[7 * NK] = f3.y;
    }
}

// -------------------- softmax + AV kernel --------------------
// block = (b,q), 512 threads, smem 77 KB
#define SOFT_THREADS 512
#define SOFT_KPT (NK / SOFT_THREADS)  // 4
#define SMS_SCORES 0
#define SMS_Q      (NH * SST)                    // 16448
#define SMS_RED    (SMS_Q + DIM)                 // 16704
#define SMS_AV     (SMS_RED + 512)               // 17216 (16B aligned)
#define SMS_TOTAL  (SMS_AV + 4 * SOFT_THREADS)   // 19264 floats

__global__ void __launch_bounds__(SOFT_THREADS, 2)
k_soft(float* __restrict__ out_attn) {
    extern __shared__ float sms[];
    float*  s_scores = sms + SMS_SCORES;
    float*  s_q      = sms + SMS_Q;
    float*  s_red    = sms + SMS_RED;
    float4* s_av     = (float4*)(sms + SMS_AV);

    int t = threadIdx.x;
    int bq = blockIdx.x;
    int b = bq >> 8, nq = bq & 255;

    if (t < DIM) s_q[t] = g_qproj[bq * DIM + t];
    __syncthreads();

    const float4* s_q4 = (const float4*)s_q;
    const float scale = 0.17677669529663687f;     // 1/sqrt(32)

    float runmax[NH];
    #pragma unroll
    for (int h = 0; h < NH; h++) runmax[h] = -1e30f;

    // ---- QK^T + add RPE ----
    #pragma unroll 1
    for (int m = 0; m < SOFT_KPT; m++) {
        int k = m * SOFT_THREADS + t;
        const float4* kv4 = (const float4*)(g_kproj + (b * NK + k) * HD);
        float acc[NH];
        #pragma unroll
        for (int h = 0; h < NH; h++) acc[h] = 0.f;
        #pragma unroll
        for (int d4 = 0; d4 < HD / 4; d4++) {
            float4 kv = kv4[d4];
            #pragma unroll
            for (int h = 0; h < NH; h++) {
                float4 q = s_q4[h * (HD / 4) + d4];
                acc[h] += q.x * kv.x + q.y * kv.y + q.z * kv.z + q.w * kv.w;
            }
        }
        const float* sp = g_scores + (size_t)bq * NH * NK + k;
        #pragma unroll
        for (int h = 0; h < NH; h++) {
            float v = acc[h] * scale + sp[h * NK];
            s_scores[h * SST + k] = v;
            runmax[h] = fmaxf(runmax[h], v);
        }
    }
    __syncthreads();

    // ---- softmax: block max ----
    int lane = t & 31, wid = t >> 5;  // 16 warps
    #pragma unroll
    for (int h = 0; h < NH; h++) {
        float v = runmax[h];
        #pragma unroll
        for (int o = 16; o; o >>= 1) v = fmaxf(v, __shfl_xor_sync(0xffffffffu, v, o));
        if (lane == 0) s_red[h * 16 + wid] = v;
    }
    __syncthreads();
    if (t < NH) {
        float v = s_red[t * 16];
        for (int w2 = 1; w2 < 16; w2++) v = fmaxf(v, s_red[t * 16 + w2]);
        s_red[128 + t] = v;
    }
    __syncthreads();

    // ---- exp sweep (float4, k = 4t) ----
    #pragma unroll
    for (int h = 0; h < NH; h++) {
        float mh = s_red[128 + h];
        float4* p = (float4*)&s_scores[h * SST + 4 * t];
        float4 v = *p;
        v.x = __expf(v.x - mh); v.y = __expf(v.y - mh);
        v.z = __expf(v.z - mh); v.w = __expf(v.w - mh);
        *p = v;
        float s = (v.x + v.y) + (v.z + v.w);
        #pragma unroll
        for (int o = 16; o; o >>= 1) s += __shfl_xor_sync(0xffffffffu, s, o);
        if (lane == 0) s_red[h * 16 + wid] = s;
    }
    __syncthreads();
    if (t < NH) {
        float v = 0.f;
        for (int w2 = 0; w2 < 16; w2++) v += s_red[t * 16 + w2];
        s_red[136 + t] = 1.0f / v;
    }
    __syncthreads();

    // ---- normalized attn writeback (float4) ----
    #pragma unroll
    for (int h = 0; h < NH; h++) {
        float r = s_red[136 + h];
        float4 v = *(const float4*)&s_scores[h * SST + 4 * t];
        v.x *= r; v.y *= r; v.z *= r; v.w *= r;
        *(float4*)&out_attn[((size_t)(b * NH + h) * NQ + nq) * NK + 4 * t] = v;
    }

    // ---- AV: thread = (kslice, head, d-group) ----
    {
        int ks = t >> 6;            // 0..7
        int rem = t & 63;
        int h  = rem >> 3;          // 0..7
        int dg = rem & 7;           // 0..7 (4 dims each)
        const float* vbase = g_vproj + b * NK * HD + dg * 4;
        const float* prow = s_scores + h * SST;
        float4 a0 = {0,0,0,0}, a1 = {0,0,0,0};
        int k0 = ks * 256;
        #pragma unroll 2
        for (int kk = 0; kk < 256; kk += 2) {
            int ka = k0 + kk, kb2 = k0 + kk + 1;
            float pa = prow[ka], pb = prow[kb2];
            float4 va = *(const float4*)(vbase + ka * HD);
            float4 vb2 = *(const float4*)(vbase + kb2 * HD);
            a0.x += pa * va.x;  a0.y += pa * va.y;  a0.z += pa * va.z;  a0.w += pa * va.w;
            a1.x += pb * vb2.x; a1.y += pb * vb2.y; a1.z += pb * vb2.z; a1.w += pb * vb2.w;
        }
        a0.x += a1.x; a0.y += a1.y; a0.z += a1.z; a0.w += a1.w;
        s_av[t] = a0;
    }
    __syncthreads();
    if (t < 256) {
        int h = t >> 5, d = t & 31;
        int dg = d >> 2, c = d & 3;
        float acc = 0.f;
        #pragma unroll
        for (int ks = 0; ks < 8; ks++)
            acc += ((const float*)&s_av[ks * 64 + h * 8 + dg])[c];
        acc *= s_red[136 + h];
        g_xmid[bq * DIM + t] = acc;
    }
}

// -------------------- output projection --------------------
__global__ void k_proj(const float* __restrict__ w, const float* __restrict__ bias,
                       float* __restrict__ out_x) {
    __shared__ float row[DIM];
    int rid = blockIdx.x;               // b*NQ + nq
    int b = rid >> 8, nq = rid & 255;
    int t = threadIdx.x;
    row[t] = g_xmid[rid * DIM + t];
    __syncthreads();
    float acc = bias[t];
    #pragma unroll 4
    for (int c = 0; c < DIM; c++) acc += row[c] * w[c * DIM + t];
    out_x[(nq * BB + b) * DIM + t] = acc;
}

// -------------------- launch --------------------
extern "C" void kernel_launch(void* const* d_in, const int* in_sizes, int n_in,
                              void* d_out, int out_size) {
    const float* query = (const float*)d_in[0];
    const float* key   = (const float*)d_in[1];
    const float* refpt = (const float*)d_in[2];
    const float* xyz   = (const float*)d_in[4];
    const float* q_w   = (const float*)d_in[5];
    const float* q_b   = (const float*)d_in[6];
    const float* k_w   = (const float*)d_in[7];
    const float* k_b   = (const float*)d_in[8];
    const float* v_w   = (const float*)d_in[9];
    const float* v_b   = (const float*)d_in[10];
    const float* p_w   = (const float*)d_in[11];
    const float* p_b   = (const float*)d_in[12];
    const float* w1    = (const float*)d_in[13];
    const float* b1    = (const float*)d_in[14];
    const float* w2    = (const float*)d_in[15];

    float* out_x    = (float*)d_out;                       // (nQ, B, DIM)
    float* out_attn = (float*)d_out + BB * NQ * DIM;       // (B, NH, nQ, nK)

    const int rpe_smem  = TBL_HALVES_PER_STAGE * 2;        // 64000 B
    const int soft_smem = SMS_TOTAL * (int)sizeof(float);  // 77056 B
    cudaFuncSetAttribute(k_rpe,  cudaFuncAttributeMaxDynamicSharedMemorySize, rpe_smem);
    cudaFuncSetAttribute(k_soft, cudaFuncAttributeMaxDynamicSharedMemorySize, soft_smem);

    k_tables<<<(NPTS * NCELL + 255) / 256, 256>>>(w1, b1, w2);
    k_qproj <<<BB * NQ, 256>>>(query, q_w, q_b);
    k_kvproj<<<BB * NK, 64>>>(key, k_w, k_b, v_w, v_b);
    k_rpe   <<<BB * NQ * 2, RPE_THREADS, rpe_smem>>>(refpt, xyz);
    k_soft  <<<BB * NQ, SOFT_THREADS, soft_smem>>>(out_attn);
    k_proj  <<<BB * NQ, 256>>>(p_w, p_b, out_x);
}